// round 14
// baseline (speedup 1.0000x reference)
#include <cuda_runtime.h>
#include <cuda_fp16.h>
#include <cstdint>

// ============================================================================
// Fused attention block via mma.sync (HMMA), fp16 hi/lo split arithmetic.
// Algebraic rewrites:
//   scores = 32*( x(WqWk^T)x^T + a_i + b_j + c )     (q/k projections gone)
//   out    = p·(v·Wp) + bp                           (ctx intermediate gone)
// Z = v·Wp computed on the side stream (hidden under scores); post-softmax
// tail is a single GEMM. Terms: 3-term (MT, t, scores), 2-term (v, Z, out).
// 128x128 tiles, 128 thr/4 warps, 64x64 warp tiles, 2 CTA/SM.
// ============================================================================

#define TOK 8192
#define DIM 1024
#define SEQ 2048
#define BATCH 4

static const long long OUT_ELEMS = (long long)TOK * DIM;
static const long long PATTN_ELEMS = (long long)BATCH * SEQ * SEQ;

// ---------------- device scratch ----------------
__device__ __half g_xhi[TOK * DIM], g_xlo[TOK * DIM];
__device__ __half g_wqsh[DIM * DIM], g_wqsl[DIM * DIM];
__device__ __half g_wksh[DIM * DIM], g_wksl[DIM * DIM];
__device__ __half g_wvTh[DIM * DIM], g_wvTl[DIM * DIM];
__device__ __half g_wpTh[DIM * DIM], g_wpTl[DIM * DIM];
__device__ float  g_mtpart[4 * DIM * DIM];
__device__ __half g_mth[DIM * DIM], g_mtl[DIM * DIM];
__device__ __half g_thi[TOK * DIM], g_tlo[TOK * DIM];
__device__ __half g_vhi[TOK * DIM];                       // v, row-major
__device__ __half g_zth[TOK * DIM], g_ztl[TOK * DIM];     // (v·Wp)^T per batch
__device__ __half g_phi[BATCH * SEQ * SEQ];
__device__ float  g_u[DIM], g_w[DIM], g_c[1];
__device__ float  g_av[TOK], g_bv[TOK];
__device__ float  g_scores_fb[BATCH * SEQ * SEQ];

// ---------------- PTX helpers ----------------
__device__ __forceinline__ uint32_t smem_u32_f(const void* p) {
    uint32_t a;
    asm("{ .reg .u64 t; cvta.to.shared.u64 t, %1; cvt.u32.u64 %0, t; }"
        : "=r"(a) : "l"(p));
    return a;
}
__device__ __forceinline__ void cp16(uint32_t dst, const void* src) {
    asm volatile("cp.async.cg.shared.global [%0], [%1], 16;" :: "r"(dst), "l"(src));
}
__device__ __forceinline__ void cp_commit() { asm volatile("cp.async.commit_group;"); }
template <int N>
__device__ __forceinline__ void cp_wait() {
    asm volatile("cp.async.wait_group %0;" :: "n"(N));
}
__device__ __forceinline__ void ldm_x4(uint32_t r[4], uint32_t addr) {
    asm volatile("ldmatrix.sync.aligned.m8n8.x4.shared.b16 {%0,%1,%2,%3}, [%4];"
                 : "=r"(r[0]), "=r"(r[1]), "=r"(r[2]), "=r"(r[3]) : "r"(addr));
}
__device__ __forceinline__ void mma16816(float c[4], const uint32_t a[4],
                                         const uint32_t b0, const uint32_t b1) {
    asm volatile(
        "mma.sync.aligned.m16n8k16.row.col.f32.f16.f16.f32 "
        "{%0,%1,%2,%3},{%4,%5,%6,%7},{%8,%9},{%0,%1,%2,%3};"
        : "+f"(c[0]), "+f"(c[1]), "+f"(c[2]), "+f"(c[3])
        : "r"(a[0]), "r"(a[1]), "r"(a[2]), "r"(a[3]), "r"(b0), "r"(b1));
}

#define PITCH 80u
#define TILE_B (128u * PITCH)            // 10240 B

// ============================================================================
// GEMM core for one 128x128 output tile.
// Kld = row stride of A/B; Kit = iterated K extent (split-K).
// WTRANS: transposed store C^T[col][row] (hi, plus lo if WLO).
// ============================================================================
template <int NS, bool ASPLIT, bool BSPLIT, bool WF32, bool HASBIAS, bool WLO,
          bool WTRANS, bool SCB>
__device__ __forceinline__ void gemm_core(
    const __half* __restrict__ Ah, const __half* __restrict__ Al,
    const __half* __restrict__ Bh, const __half* __restrict__ Bl,
    const float* __restrict__ bias,
    float* __restrict__ Cf, __half* __restrict__ Chi, __half* __restrict__ Clo,
    int N, int Kld, int Kit, float alpha, int row0, int col0, long long cOff,
    const float* __restrict__ av, const float* __restrict__ bv,
    const float* __restrict__ cb)
{
    constexpr uint32_t OF_AH = 0u;
    constexpr uint32_t OF_BH = TILE_B;
    constexpr uint32_t OF_AL = 2u * TILE_B;
    constexpr uint32_t OF_BL = (ASPLIT ? 3u : 2u) * TILE_B;
    constexpr uint32_t STG_SZ = (2u + (ASPLIT ? 1u : 0u) + (BSPLIT ? 1u : 0u)) * TILE_B;

    extern __shared__ char smem_raw[];
    const uint32_t base = smem_u32_f(smem_raw);
    const int tid = threadIdx.x;
    const int warp = tid >> 5, lane = tid & 31;

    long long aOff[4], bOff[4];
    uint32_t dOff[4];
#pragma unroll
    for (int j = 0; j < 4; j++) {
        int c = tid + j * 128;
        int r = c >> 2, q = c & 3;
        aOff[j] = (long long)(row0 + r) * Kld + q * 8;
        bOff[j] = (long long)(col0 + r) * Kld + q * 8;
        dOff[j] = (uint32_t)r * PITCH + (uint32_t)q * 16u;
    }

    const int m0 = (warp & 1) * 64, n0 = (warp >> 1) * 64;
    const uint32_t aLane = (uint32_t)(lane & 15) * PITCH + (uint32_t)(lane >> 4) * 16u;
    const uint32_t bLane = (uint32_t)((lane & 7) + ((lane >> 4) << 3)) * PITCH +
                           (uint32_t)((lane >> 3) & 1) * 16u;

    float acc[4][8][4];
#pragma unroll
    for (int i = 0; i < 4; i++)
#pragma unroll
        for (int j = 0; j < 8; j++)
#pragma unroll
            for (int e = 0; e < 4; e++) acc[i][j][e] = 0.f;

    const int nk = Kit >> 5;

#pragma unroll
    for (int s = 0; s < NS - 1; s++) {
        uint32_t sb = base + (uint32_t)s * STG_SZ;
        long long k0 = (long long)s * 32;
#pragma unroll
        for (int j = 0; j < 4; j++) {
            cp16(sb + OF_AH + dOff[j], Ah + aOff[j] + k0);
            if (ASPLIT) cp16(sb + OF_AL + dOff[j], Al + aOff[j] + k0);
            cp16(sb + OF_BH + dOff[j], Bh + bOff[j] + k0);
            if (BSPLIT) cp16(sb + OF_BL + dOff[j], Bl + bOff[j] + k0);
        }
        cp_commit();
    }

    for (int i = 0; i < nk; i++) {
        const int pend = (nk - 1 - i < NS - 2) ? (nk - 1 - i) : (NS - 2);
        if (pend >= 2)      cp_wait<2>();
        else if (pend == 1) cp_wait<1>();
        else                cp_wait<0>();
        __syncthreads();

        if (i + NS - 1 < nk) {
            const int s = (i + NS - 1) % NS;
            uint32_t sb = base + (uint32_t)s * STG_SZ;
            long long k0 = (long long)(i + NS - 1) * 32;
#pragma unroll
            for (int j = 0; j < 4; j++) {
                cp16(sb + OF_AH + dOff[j], Ah + aOff[j] + k0);
                if (ASPLIT) cp16(sb + OF_AL + dOff[j], Al + aOff[j] + k0);
                cp16(sb + OF_BH + dOff[j], Bh + bOff[j] + k0);
                if (BSPLIT) cp16(sb + OF_BL + dOff[j], Bl + bOff[j] + k0);
            }
            cp_commit();
        }

        const uint32_t sb = base + (uint32_t)(i % NS) * STG_SZ;
#pragma unroll
        for (int ks = 0; ks < 2; ks++) {
            const uint32_t kb = (uint32_t)ks * 32u;
            uint32_t ah[4][4], al[4][4], bh[4][4], bl[4][4];
#pragma unroll
            for (int mf = 0; mf < 4; mf++) {
                uint32_t ro = (uint32_t)(m0 + mf * 16) * PITCH + kb + aLane;
                ldm_x4(ah[mf], sb + OF_AH + ro);
                if (ASPLIT) ldm_x4(al[mf], sb + OF_AL + ro);
            }
#pragma unroll
            for (int q = 0; q < 4; q++) {
                uint32_t ro = (uint32_t)(n0 + q * 16) * PITCH + kb + bLane;
                ldm_x4(bh[q], sb + OF_BH + ro);
                if (BSPLIT) ldm_x4(bl[q], sb + OF_BL + ro);
            }
#pragma unroll
            for (int mf = 0; mf < 4; mf++)
#pragma unroll
                for (int nf = 0; nf < 8; nf++) {
                    const int q = nf >> 1, h = (nf & 1) * 2;
                    mma16816(acc[mf][nf], ah[mf], bh[q][h], bh[q][h + 1]);
                    if (ASPLIT) mma16816(acc[mf][nf], al[mf], bh[q][h], bh[q][h + 1]);
                    if (BSPLIT) mma16816(acc[mf][nf], ah[mf], bl[q][h], bl[q][h + 1]);
                }
        }
    }

    // ---- epilogue ----
    const int tg = lane >> 2, tl = lane & 3;
    const float c0 = SCB ? __ldg(cb) : 0.f;
#pragma unroll
    for (int mf = 0; mf < 4; mf++) {
#pragma unroll
        for (int nf = 0; nf < 8; nf++) {
            const int col = col0 + n0 + nf * 8 + tl * 2;
            float b0 = 0.f, b1 = 0.f;
            if (HASBIAS) { b0 = __ldg(bias + col); b1 = __ldg(bias + col + 1); }
            float bc0 = 0.f, bc1 = 0.f;
            if (SCB) { bc0 = __ldg(bv + col) + c0; bc1 = __ldg(bv + col + 1) + c0; }
#pragma unroll
            for (int hrow = 0; hrow < 2; hrow++) {
                const int row = row0 + m0 + mf * 16 + tg + hrow * 8;
                float v0, v1;
                if (SCB) {
                    const float ar = __ldg(av + row);
                    v0 = (acc[mf][nf][hrow * 2 + 0] + ar + bc0) * alpha;
                    v1 = (acc[mf][nf][hrow * 2 + 1] + ar + bc1) * alpha;
                } else {
                    v0 = acc[mf][nf][hrow * 2 + 0] * alpha + b0;
                    v1 = acc[mf][nf][hrow * 2 + 1] * alpha + b1;
                }
                if (WTRANS) {
                    __half h0 = __float2half_rn(v0);
                    __half h1 = __float2half_rn(v1);
                    Chi[cOff + (long long)col * SEQ + row] = h0;
                    Chi[cOff + (long long)(col + 1) * SEQ + row] = h1;
                    if (WLO) {
                        Clo[cOff + (long long)col * SEQ + row] =
                            __float2half_rn(v0 - __half2float(h0));
                        Clo[cOff + (long long)(col + 1) * SEQ + row] =
                            __float2half_rn(v1 - __half2float(h1));
                    }
                } else {
                    const long long off = cOff + (long long)row * N + col;
                    if (WF32) {
                        float2 o; o.x = v0; o.y = v1;
                        *(float2*)(Cf + off) = o;
                    } else {
                        __half h0 = __float2half_rn(v0);
                        __half h1 = __float2half_rn(v1);
                        __half2 th; th.x = h0; th.y = h1;
                        *(__half2*)(Chi + off) = th;
                        if (WLO) {
                            __half2 tlh;
                            tlh.x = __float2half_rn(v0 - __half2float(h0));
                            tlh.y = __float2half_rn(v1 - __half2float(h1));
                            *(__half2*)(Clo + off) = tlh;
                        }
                    }
                }
            }
        }
    }
}

// ---------------- persistent GEMM over (ntz, nty, ntx) tiles ----------------
template <int NS, bool ASPLIT, bool BSPLIT, bool WF32, bool HASBIAS, bool WLO,
          bool SCB>
__global__ void __launch_bounds__(128) mma_gemm_p(
    const __half* __restrict__ Ah_g, const __half* __restrict__ Al_g,
    const __half* __restrict__ Bh_g, const __half* __restrict__ Bl_g,
    const float* __restrict__ bias,
    float* __restrict__ Cf, __half* __restrict__ Chi, __half* __restrict__ Clo,
    int N, int Kld, int Kit, float alpha,
    long long sA, long long sB, long long sC,
    int ntx, int nty, int ntz,
    const float* __restrict__ av, const float* __restrict__ bv,
    const float* __restrict__ cb)
{
    const int total = ntx * nty * ntz;
    const int nxy = ntx * nty;
    for (int t = blockIdx.x; t < total; t += gridDim.x) {
        const int tz = t / nxy;
        const int r = t - tz * nxy;
        const int ty = r / ntx;
        const int tx = r - ty * ntx;
        __syncthreads();
        gemm_core<NS, ASPLIT, BSPLIT, WF32, HASBIAS, WLO, false, SCB>(
            Ah_g + (long long)tz * sA, ASPLIT ? (Al_g + (long long)tz * sA) : nullptr,
            Bh_g + (long long)tz * sB, BSPLIT ? (Bl_g + (long long)tz * sB) : nullptr,
            bias, Cf, Chi, Clo, N, Kld, Kit, alpha,
            ty * 128, tx * 128, (long long)tz * sC,
            SCB ? (av + (long long)tz * SEQ) : nullptr,
            SCB ? (bv + (long long)tz * SEQ) : nullptr, cb);
    }
}

// persistent Z = v @ Wp (2-term, 3-stage, TRANSPOSED hi+lo out -> Z^T[b][d][t])
__global__ void __launch_bounds__(128) z_gemm_p(
    const __half* __restrict__ vhi,
    const __half* __restrict__ wpTh, const __half* __restrict__ wpTl,
    __half* __restrict__ zth, __half* __restrict__ ztl,
    int ntx, int nty)
{
    const int total = ntx * nty;
    for (int t = blockIdx.x; t < total; t += gridDim.x) {
        const int ty = t / ntx;
        const int tx = t - ty * ntx;
        __syncthreads();
        const long long batch = (long long)((ty * 128) >> 11);
        gemm_core<3, false, true, false, false, true, true, false>(
            vhi, nullptr, wpTh, wpTl, nullptr,
            nullptr, zth, ztl, DIM, DIM, DIM, 1.f,
            ty * 128, tx * 128, batch * SEQ * (DIM - 1),
            nullptr, nullptr, nullptr);
    }
}

// smem budgets
#define SMEM_3T  (2 * 4 * 10240)        // 81920
#define SMEM_2T  (3 * 3 * 10240)        // 92160

// ============================================================================
// helper kernels
// ============================================================================
__global__ void __launch_bounds__(256) convert_split_kernel(
    const float* __restrict__ in, __half* __restrict__ hi,
    __half* __restrict__ lo, long long n4)
{
    long long i = (long long)blockIdx.x * 256 + threadIdx.x;
    if (i >= n4) return;
    float4 v = ((const float4*)in)[i];
    __half h0 = __float2half_rn(v.x), h1 = __float2half_rn(v.y);
    __half h2 = __float2half_rn(v.z), h3 = __float2half_rn(v.w);
    __half2 a, b; a.x = h0; a.y = h1; b.x = h2; b.y = h3;
    ((__half2*)hi)[i * 2 + 0] = a;
    ((__half2*)hi)[i * 2 + 1] = b;
    __half2 c, d;
    c.x = __float2half_rn(v.x - __half2float(h0));
    c.y = __float2half_rn(v.y - __half2float(h1));
    d.x = __float2half_rn(v.z - __half2float(h2));
    d.y = __float2half_rn(v.w - __half2float(h3));
    ((__half2*)lo)[i * 2 + 0] = c;
    ((__half2*)lo)[i * 2 + 1] = d;
}

__global__ void __launch_bounds__(256) mt_reduce_kernel(
    const float* __restrict__ part, __half* __restrict__ hi,
    __half* __restrict__ lo)
{
    const long long n4 = (long long)DIM * DIM / 4;
    long long i = (long long)blockIdx.x * 256 + threadIdx.x;
    if (i >= n4) return;
    const long long stride4 = n4;
    float4 a = ((const float4*)part)[i];
    float4 b = ((const float4*)part)[i + stride4];
    float4 c = ((const float4*)part)[i + 2 * stride4];
    float4 d = ((const float4*)part)[i + 3 * stride4];
    float4 s;
    s.x = (a.x + b.x) + (c.x + d.x);
    s.y = (a.y + b.y) + (c.y + d.y);
    s.z = (a.z + b.z) + (c.z + d.z);
    s.w = (a.w + b.w) + (c.w + d.w);
    __half h0 = __float2half_rn(s.x), h1 = __float2half_rn(s.y);
    __half h2 = __float2half_rn(s.z), h3 = __float2half_rn(s.w);
    __half2 p, q; p.x = h0; p.y = h1; q.x = h2; q.y = h3;
    ((__half2*)hi)[i * 2 + 0] = p;
    ((__half2*)hi)[i * 2 + 1] = q;
    __half2 r, t;
    r.x = __float2half_rn(s.x - __half2float(h0));
    r.y = __float2half_rn(s.y - __half2float(h1));
    t.x = __float2half_rn(s.z - __half2float(h2));
    t.y = __float2half_rn(s.w - __half2float(h3));
    ((__half2*)lo)[i * 2 + 0] = r;
    ((__half2*)lo)[i * 2 + 1] = t;
}

__global__ void __launch_bounds__(256) transpose_split_kernel(
    const float* __restrict__ in, __half* __restrict__ hi,
    __half* __restrict__ lo, int R, int C)
{
    __shared__ float t[32][33];
    const int c0 = blockIdx.x * 32, r0 = blockIdx.y * 32;
    const int tx = threadIdx.x & 31, ty = threadIdx.x >> 5;
#pragma unroll
    for (int j = 0; j < 4; j++)
        t[ty + j * 8][tx] = in[(long long)(r0 + ty + j * 8) * C + c0 + tx];
    __syncthreads();
#pragma unroll
    for (int j = 0; j < 4; j++) {
        int oc = c0 + ty + j * 8;
        float v = t[tx][ty + j * 8];
        long long o = (long long)oc * R + r0 + tx;
        __half h = __float2half_rn(v);
        hi[o] = h;
        lo[o] = __float2half_rn(v - __half2float(h));
    }
}

__global__ void __launch_bounds__(256) uvw_kernel(
    const float* __restrict__ wq, const float* __restrict__ wk,
    const float* __restrict__ bq, const float* __restrict__ bk,
    float* __restrict__ u, float* __restrict__ w, float* __restrict__ cb)
{
    const int d = blockIdx.x * 2 + (threadIdx.x >> 7);
    const int tid = threadIdx.x & 127;
    float su = 0.f, sw = 0.f;
    const float4* wq4 = (const float4*)(wq + (long long)d * DIM);
    const float4* wk4 = (const float4*)(wk + (long long)d * DIM);
    const float4* bk4 = (const float4*)bk;
    const float4* bq4 = (const float4*)bq;
    for (int f = tid; f < DIM / 4; f += 128) {
        float4 a = wq4[f], b = bk4[f];
        su += a.x * b.x + a.y * b.y + a.z * b.z + a.w * b.w;
        float4 c = wk4[f], e = bq4[f];
        sw += c.x * e.x + c.y * e.y + c.z * e.z + c.w * e.w;
    }
#pragma unroll
    for (int o = 16; o; o >>= 1) {
        su += __shfl_xor_sync(0xffffffffu, su, o);
        sw += __shfl_xor_sync(0xffffffffu, sw, o);
    }
    __shared__ float r1[2][4], r2[2][4];
    const int half = threadIdx.x >> 7, wrp = (threadIdx.x >> 5) & 3;
    if ((tid & 31) == 0) { r1[half][wrp] = su; r2[half][wrp] = sw; }
    __syncthreads();
    if (tid == 0) {
        u[d] = (r1[half][0] + r1[half][1]) + (r1[half][2] + r1[half][3]);
        w[d] = (r2[half][0] + r2[half][1]) + (r2[half][2] + r2[half][3]);
    }
    if (d == 0 && tid == 0) {
        float c = 0.f;
        for (int f = 0; f < DIM; f++) c += bq[f] * bk[f];
        cb[0] = c;
    }
}

__global__ void __launch_bounds__(256) av_kernel(
    const float* __restrict__ x, const float* __restrict__ u,
    const float* __restrict__ w, float* __restrict__ av, float* __restrict__ bv)
{
    const long long i = blockIdx.x;
    const float* xr = x + i * DIM;
    const int tid = threadIdx.x;
    float sa = 0.f, sb = 0.f;
    for (int d = tid; d < DIM; d += 256) {
        float xv = xr[d];
        sa += xv * u[d];
        sb += xv * w[d];
    }
    __shared__ float r1[256], r2[256];
    r1[tid] = sa; r2[tid] = sb;
    __syncthreads();
    for (int s = 128; s; s >>= 1) {
        if (tid < s) { r1[tid] += r1[tid + s]; r2[tid] += r2[tid + s]; }
        __syncthreads();
    }
    if (tid == 0) { av[i] = r1[0]; bv[i] = r2[0]; }
}

__global__ void __launch_bounds__(256) softmax2048_kernel(
    float* __restrict__ p, __half* __restrict__ phi)
{
    const long long roff = (long long)blockIdx.x * 2048;
    float* row = p + roff;
    const int tid = threadIdx.x;

    float4 v0 = ((const float4*)row)[tid];
    float4 v1 = ((const float4*)row)[tid + 256];

    float m = fmaxf(fmaxf(fmaxf(v0.x, v0.y), fmaxf(v0.z, v0.w)),
                    fmaxf(fmaxf(v1.x, v1.y), fmaxf(v1.z, v1.w)));
    __shared__ float red[8];
#pragma unroll
    for (int o = 16; o; o >>= 1) m = fmaxf(m, __shfl_xor_sync(0xffffffffu, m, o));
    if ((tid & 31) == 0) red[tid >> 5] = m;
    __syncthreads();
    m = red[0];
#pragma unroll
    for (int i = 1; i < 8; i++) m = fmaxf(m, red[i]);
    __syncthreads();

    v0.x = expf(v0.x - m); v0.y = expf(v0.y - m);
    v0.z = expf(v0.z - m); v0.w = expf(v0.w - m);
    v1.x = expf(v1.x - m); v1.y = expf(v1.y - m);
    v1.z = expf(v1.z - m); v1.w = expf(v1.w - m);

    float s = (v0.x + v0.y) + (v0.z + v0.w) + (v1.x + v1.y) + (v1.z + v1.w);
#pragma unroll
    for (int o = 16; o; o >>= 1) s += __shfl_xor_sync(0xffffffffu, s, o);
    if ((tid & 31) == 0) red[tid >> 5] = s;
    __syncthreads();
    s = ((red[0] + red[1]) + (red[2] + red[3])) +
        ((red[4] + red[5]) + (red[6] + red[7]));
    float inv = 1.0f / s;

    v0.x *= inv; v0.y *= inv; v0.z *= inv; v0.w *= inv;
    v1.x *= inv; v1.y *= inv; v1.z *= inv; v1.w *= inv;

    ((float4*)row)[tid] = v0;
    ((float4*)row)[tid + 256] = v1;

    const float vv[8] = {v0.x, v0.y, v0.z, v0.w, v1.x, v1.y, v1.z, v1.w};
    const long long off[2] = {roff + (long long)tid * 4,
                              roff + (long long)(tid + 256) * 4};
#pragma unroll
    for (int hseg = 0; hseg < 2; hseg++) {
#pragma unroll
        for (int g = 0; g < 2; g++) {
            __half2 th;
            th.x = __float2half_rn(vv[hseg * 4 + g * 2]);
            th.y = __float2half_rn(vv[hseg * 4 + g * 2 + 1]);
            *(__half2*)(phi + off[hseg] + g * 2) = th;
        }
    }
}

// ============================================================================
// host launcher
// ============================================================================
extern "C" void kernel_launch(void* const* d_in, const int* in_sizes, int n_in,
                              void* d_out, int out_size)
{
    const float* x  = (const float*)d_in[0];
    const float* wq = (const float*)d_in[1];
    const float* bq = (const float*)d_in[2];
    const float* wk = (const float*)d_in[3];
    const float* bk = (const float*)d_in[4];
    const float* wv = (const float*)d_in[5];
    const float* bv = (const float*)d_in[6];
    const float* wp = (const float*)d_in[7];
    const float* bp = (const float*)d_in[8];
    float* out = (float*)d_out;

#define SYM(p, s) void* p##_; cudaGetSymbolAddress(&p##_, s);
    SYM(xhi, g_xhi) SYM(xlo, g_xlo)
    SYM(wqsh, g_wqsh) SYM(wqsl, g_wqsl)
    SYM(wksh, g_wksh) SYM(wksl, g_wksl)
    SYM(wvth, g_wvTh) SYM(wvtl, g_wvTl)
    SYM(wpth, g_wpTh) SYM(wptl, g_wpTl)
    SYM(mtp, g_mtpart)
    SYM(mth, g_mth) SYM(mtl, g_mtl)
    SYM(thi, g_thi) SYM(tlo, g_tlo)
    SYM(vhi, g_vhi)
    SYM(zth, g_zth) SYM(ztl, g_ztl)
    SYM(phi, g_phi)
    SYM(uu, g_u) SYM(ww, g_w) SYM(cc, g_c)
    SYM(avv, g_av) SYM(bvv, g_bv)
    SYM(sfb, g_scores_fb)
#undef SYM
#define HF(p) ((__half*)p##_)

    float* pattn = (out_size >= (long long)(OUT_ELEMS + PATTN_ELEMS))
                       ? (out + OUT_ELEMS) : (float*)sfb_;

    static int nPersist = 0;
    static cudaStream_t s1 = nullptr;
    static cudaEvent_t evFork = nullptr, evX = nullptr, evAux = nullptr,
                       evJoin = nullptr;
    if (nPersist == 0) {
        int nsm = 148;
        cudaDeviceGetAttribute(&nsm, cudaDevAttrMultiProcessorCount, 0);
        nPersist = 2 * nsm;
        cudaStreamCreateWithFlags(&s1, cudaStreamNonBlocking);
        cudaEventCreateWithFlags(&evFork, cudaEventDisableTiming);
        cudaEventCreateWithFlags(&evX, cudaEventDisableTiming);
        cudaEventCreateWithFlags(&evAux, cudaEventDisableTiming);
        cudaEventCreateWithFlags(&evJoin, cudaEventDisableTiming);

        cudaFuncSetAttribute(z_gemm_p, cudaFuncAttributeMaxDynamicSharedMemorySize, SMEM_2T);
        cudaFuncSetAttribute(mma_gemm_p<2, true,  true,  true,  false, false, false>, cudaFuncAttributeMaxDynamicSharedMemorySize, SMEM_3T);
        cudaFuncSetAttribute(mma_gemm_p<2, true,  true,  false, false, true,  false>, cudaFuncAttributeMaxDynamicSharedMemorySize, SMEM_3T);
        cudaFuncSetAttribute(mma_gemm_p<2, true,  true,  true,  false, false, true >, cudaFuncAttributeMaxDynamicSharedMemorySize, SMEM_3T);
        cudaFuncSetAttribute(mma_gemm_p<3, false, true,  false, true,  false, false>, cudaFuncAttributeMaxDynamicSharedMemorySize, SMEM_2T);
        cudaFuncSetAttribute(mma_gemm_p<3, false, true,  true,  true,  false, false>, cudaFuncAttributeMaxDynamicSharedMemorySize, SMEM_2T);
    }
    cudaStream_t s0 = 0;

    // ---- fork ----
    cudaEventRecord(evFork, s0);
    cudaStreamWaitEvent(s1, evFork, 0);

    // ---- s1: x split, aux, v = x@Wv, Z = v@Wp (transposed hi/lo) ----
    convert_split_kernel<<<(TOK * DIM / 4 + 255) / 256, 256, 0, s1>>>(
        x, HF(xhi), HF(xlo), TOK * DIM / 4);
    cudaEventRecord(evX, s1);
    uvw_kernel<<<DIM / 2, 256, 0, s1>>>(wq, wk, bq, bk,
                                        (float*)uu_, (float*)ww_, (float*)cc_);
    av_kernel<<<TOK, 256, 0, s1>>>(x, (float*)uu_, (float*)ww_, (float*)avv_, (float*)bvv_);
    cudaEventRecord(evAux, s1);
    dim3 gW(DIM / 32, DIM / 32, 1);
    transpose_split_kernel<<<gW, 256, 0, s1>>>(wv, HF(wvth), HF(wvtl), DIM, DIM);
    transpose_split_kernel<<<gW, 256, 0, s1>>>(wp, HF(wpth), HF(wptl), DIM, DIM);
    // v = x @ Wv + bv (2-term, hi out, row-major)
    mma_gemm_p<3, false, true, false, true, false, false><<<nPersist, 128, SMEM_2T, s1>>>(
        HF(xhi), nullptr, HF(wvth), HF(wvtl), bv,
        nullptr, HF(vhi), nullptr, DIM, DIM, DIM, 1.f, 0, 0, 0,
        DIM / 128, TOK / 128, 1, nullptr, nullptr, nullptr);
    // Z^T = (v @ Wp)^T per batch (2-term, hi+lo, transposed store)
    z_gemm_p<<<nPersist, 128, SMEM_2T, s1>>>(
        HF(vhi), HF(wpth), HF(wptl), HF(zth), HF(ztl), DIM / 128, TOK / 128);
    cudaEventRecord(evJoin, s1);

    // ---- s0: critical chain (wq/wk splits -> MT split-K -> reduce -> t) ----
    convert_split_kernel<<<(DIM * DIM / 4 + 255) / 256, 256, 0, s0>>>(
        wq, HF(wqsh), HF(wqsl), DIM * DIM / 4);
    convert_split_kernel<<<(DIM * DIM / 4 + 255) / 256, 256, 0, s0>>>(
        wk, HF(wksh), HF(wksl), DIM * DIM / 4);

    mma_gemm_p<2, true, true, true, false, false, false><<<nPersist, 128, SMEM_3T, s0>>>(
        HF(wksh), HF(wksl), HF(wqsh), HF(wqsl), nullptr,
        (float*)mtp_, nullptr, nullptr, DIM, DIM, DIM / 4, 1.f,
        DIM / 4, DIM / 4, (long long)DIM * DIM,
        DIM / 128, DIM / 128, 4, nullptr, nullptr, nullptr);
    mt_reduce_kernel<<<(DIM * DIM / 4 + 255) / 256, 256, 0, s0>>>(
        (const float*)mtp_, HF(mth), HF(mtl));

    cudaStreamWaitEvent(s0, evX, 0);
    mma_gemm_p<2, true, true, false, false, true, false><<<nPersist, 128, SMEM_3T, s0>>>(
        HF(xhi), HF(xlo), HF(mth), HF(mtl), nullptr,
        nullptr, HF(thi), HF(tlo), DIM, DIM, DIM, 1.f, 0, 0, 0,
        DIM / 128, TOK / 128, 1, nullptr, nullptr, nullptr);

    // ---- scores (waits only on aux) ----
    cudaStreamWaitEvent(s0, evAux, 0);
    mma_gemm_p<2, true, true, true, false, false, true><<<nPersist, 128, SMEM_3T, s0>>>(
        HF(thi), HF(tlo), HF(xhi), HF(xlo), nullptr, pattn, nullptr, nullptr,
        SEQ, DIM, DIM, 32.f,
        (long long)SEQ * DIM, (long long)SEQ * DIM, (long long)SEQ * SEQ,
        SEQ / 128, SEQ / 128, BATCH,
        (const float*)avv_, (const float*)bvv_, (const float*)cc_);

    softmax2048_kernel<<<TOK, 256, 0, s0>>>(pattn, HF(phi));

    // ---- single post-softmax GEMM: out = p_hi @ Z + bp ----
    cudaStreamWaitEvent(s0, evJoin, 0);
    mma_gemm_p<3, false, true, true, true, false, false><<<nPersist, 128, SMEM_2T, s0>>>(
        HF(phi), nullptr, HF(zth), HF(ztl), bp, out, nullptr, nullptr,
        DIM, SEQ, SEQ, 1.f,
        (long long)SEQ * SEQ, (long long)DIM * SEQ, (long long)SEQ * DIM,
        DIM / 128, SEQ / 128, BATCH, nullptr, nullptr, nullptr);
}

// round 15
// speedup vs baseline: 1.2495x; 1.2495x over previous
#include <cuda_runtime.h>
#include <cuda_fp16.h>
#include <cstdint>

// ============================================================================
// Fused attention block via mma.sync (HMMA), fp16 hi/lo split arithmetic.
// Algebraic rewrites:
//   scores = 32*( x(WqWk^T)x^T + a_i + b_j + c )   (q/k projections gone)
//   out    = p·Z + bp,  Z = x·(WvWp) + Wp^T bv     (v AND ctx intermediates gone)
// WZT = Wp^T Wv^T precomputed split-K; Z computed on side stream; the
// post-softmax tail is ONE 1-term GEMM.
// Terms: 3-term (MT, WZT, t, scores), 2-term (Z), 1-term (out).
// 128x128 tiles, 128 thr/4 warps, 64x64 warp tiles, 2 CTA/SM.
// ============================================================================

#define TOK 8192
#define DIM 1024
#define SEQ 2048
#define BATCH 4

static const long long OUT_ELEMS = (long long)TOK * DIM;
static const long long PATTN_ELEMS = (long long)BATCH * SEQ * SEQ;

// ---------------- device scratch ----------------
__device__ __half g_xhi[TOK * DIM], g_xlo[TOK * DIM];
__device__ __half g_wqsh[DIM * DIM], g_wqsl[DIM * DIM];
__device__ __half g_wksh[DIM * DIM], g_wksl[DIM * DIM];
__device__ __half g_wvsh[DIM * DIM], g_wvsl[DIM * DIM];   // Wv straight split
__device__ __half g_wpTh[DIM * DIM], g_wpTl[DIM * DIM];   // Wp^T split
__device__ float  g_mtpart[4 * DIM * DIM];
__device__ float  g_wzpart[4 * DIM * DIM];
__device__ __half g_mth[DIM * DIM], g_mtl[DIM * DIM];
__device__ __half g_wzth[DIM * DIM], g_wztl[DIM * DIM];   // WZT = Wp^T Wv^T
__device__ __half g_thi[TOK * DIM], g_tlo[TOK * DIM];
__device__ __half g_zth[TOK * DIM];                       // Z^T[b][d][t] hi
__device__ __half g_phi[BATCH * SEQ * SEQ];
__device__ float  g_u[DIM], g_w[DIM], g_c[1], g_bz[DIM];
__device__ float  g_av[TOK], g_bv[TOK];
__device__ float  g_scores_fb[BATCH * SEQ * SEQ];

// ---------------- PTX helpers ----------------
__device__ __forceinline__ uint32_t smem_u32_f(const void* p) {
    uint32_t a;
    asm("{ .reg .u64 t; cvta.to.shared.u64 t, %1; cvt.u32.u64 %0, t; }"
        : "=r"(a) : "l"(p));
    return a;
}
__device__ __forceinline__ void cp16(uint32_t dst, const void* src) {
    asm volatile("cp.async.cg.shared.global [%0], [%1], 16;" :: "r"(dst), "l"(src));
}
__device__ __forceinline__ void cp_commit() { asm volatile("cp.async.commit_group;"); }
template <int N>
__device__ __forceinline__ void cp_wait() {
    asm volatile("cp.async.wait_group %0;" :: "n"(N));
}
__device__ __forceinline__ void ldm_x4(uint32_t r[4], uint32_t addr) {
    asm volatile("ldmatrix.sync.aligned.m8n8.x4.shared.b16 {%0,%1,%2,%3}, [%4];"
                 : "=r"(r[0]), "=r"(r[1]), "=r"(r[2]), "=r"(r[3]) : "r"(addr));
}
__device__ __forceinline__ void mma16816(float c[4], const uint32_t a[4],
                                         const uint32_t b0, const uint32_t b1) {
    asm volatile(
        "mma.sync.aligned.m16n8k16.row.col.f32.f16.f16.f32 "
        "{%0,%1,%2,%3},{%4,%5,%6,%7},{%8,%9},{%0,%1,%2,%3};"
        : "+f"(c[0]), "+f"(c[1]), "+f"(c[2]), "+f"(c[3])
        : "r"(a[0]), "r"(a[1]), "r"(a[2]), "r"(a[3]), "r"(b0), "r"(b1));
}

#define PITCH 80u
#define TILE_B (128u * PITCH)            // 10240 B

// ============================================================================
// GEMM core for one 128x128 output tile.
// ============================================================================
template <int NS, bool ASPLIT, bool BSPLIT, bool WF32, bool HASBIAS, bool WLO,
          bool WTRANS, bool SCB>
__device__ __forceinline__ void gemm_core(
    const __half* __restrict__ Ah, const __half* __restrict__ Al,
    const __half* __restrict__ Bh, const __half* __restrict__ Bl,
    const float* __restrict__ bias,
    float* __restrict__ Cf, __half* __restrict__ Chi, __half* __restrict__ Clo,
    int N, int Kld, int Kit, float alpha, int row0, int col0, long long cOff,
    const float* __restrict__ av, const float* __restrict__ bv,
    const float* __restrict__ cb)
{
    constexpr uint32_t OF_AH = 0u;
    constexpr uint32_t OF_BH = TILE_B;
    constexpr uint32_t OF_AL = 2u * TILE_B;
    constexpr uint32_t OF_BL = (ASPLIT ? 3u : 2u) * TILE_B;
    constexpr uint32_t STG_SZ = (2u + (ASPLIT ? 1u : 0u) + (BSPLIT ? 1u : 0u)) * TILE_B;

    extern __shared__ char smem_raw[];
    const uint32_t base = smem_u32_f(smem_raw);
    const int tid = threadIdx.x;
    const int warp = tid >> 5, lane = tid & 31;

    long long aOff[4], bOff[4];
    uint32_t dOff[4];
#pragma unroll
    for (int j = 0; j < 4; j++) {
        int c = tid + j * 128;
        int r = c >> 2, q = c & 3;
        aOff[j] = (long long)(row0 + r) * Kld + q * 8;
        bOff[j] = (long long)(col0 + r) * Kld + q * 8;
        dOff[j] = (uint32_t)r * PITCH + (uint32_t)q * 16u;
    }

    const int m0 = (warp & 1) * 64, n0 = (warp >> 1) * 64;
    const uint32_t aLane = (uint32_t)(lane & 15) * PITCH + (uint32_t)(lane >> 4) * 16u;
    const uint32_t bLane = (uint32_t)((lane & 7) + ((lane >> 4) << 3)) * PITCH +
                           (uint32_t)((lane >> 3) & 1) * 16u;

    float acc[4][8][4];
#pragma unroll
    for (int i = 0; i < 4; i++)
#pragma unroll
        for (int j = 0; j < 8; j++)
#pragma unroll
            for (int e = 0; e < 4; e++) acc[i][j][e] = 0.f;

    const int nk = Kit >> 5;

#pragma unroll
    for (int s = 0; s < NS - 1; s++) {
        uint32_t sb = base + (uint32_t)s * STG_SZ;
        long long k0 = (long long)s * 32;
#pragma unroll
        for (int j = 0; j < 4; j++) {
            cp16(sb + OF_AH + dOff[j], Ah + aOff[j] + k0);
            if (ASPLIT) cp16(sb + OF_AL + dOff[j], Al + aOff[j] + k0);
            cp16(sb + OF_BH + dOff[j], Bh + bOff[j] + k0);
            if (BSPLIT) cp16(sb + OF_BL + dOff[j], Bl + bOff[j] + k0);
        }
        cp_commit();
    }

    for (int i = 0; i < nk; i++) {
        const int pend = (nk - 1 - i < NS - 2) ? (nk - 1 - i) : (NS - 2);
        if (pend >= 2)      cp_wait<2>();
        else if (pend == 1) cp_wait<1>();
        else                cp_wait<0>();
        __syncthreads();

        if (i + NS - 1 < nk) {
            const int s = (i + NS - 1) % NS;
            uint32_t sb = base + (uint32_t)s * STG_SZ;
            long long k0 = (long long)(i + NS - 1) * 32;
#pragma unroll
            for (int j = 0; j < 4; j++) {
                cp16(sb + OF_AH + dOff[j], Ah + aOff[j] + k0);
                if (ASPLIT) cp16(sb + OF_AL + dOff[j], Al + aOff[j] + k0);
                cp16(sb + OF_BH + dOff[j], Bh + bOff[j] + k0);
                if (BSPLIT) cp16(sb + OF_BL + dOff[j], Bl + bOff[j] + k0);
            }
            cp_commit();
        }

        const uint32_t sb = base + (uint32_t)(i % NS) * STG_SZ;
#pragma unroll
        for (int ks = 0; ks < 2; ks++) {
            const uint32_t kb = (uint32_t)ks * 32u;
            uint32_t ah[4][4], al[4][4], bh[4][4], bl[4][4];
#pragma unroll
            for (int mf = 0; mf < 4; mf++) {
                uint32_t ro = (uint32_t)(m0 + mf * 16) * PITCH + kb + aLane;
                ldm_x4(ah[mf], sb + OF_AH + ro);
                if (ASPLIT) ldm_x4(al[mf], sb + OF_AL + ro);
            }
#pragma unroll
            for (int q = 0; q < 4; q++) {
                uint32_t ro = (uint32_t)(n0 + q * 16) * PITCH + kb + bLane;
                ldm_x4(bh[q], sb + OF_BH + ro);
                if (BSPLIT) ldm_x4(bl[q], sb + OF_BL + ro);
            }
#pragma unroll
            for (int mf = 0; mf < 4; mf++)
#pragma unroll
                for (int nf = 0; nf < 8; nf++) {
                    const int q = nf >> 1, h = (nf & 1) * 2;
                    mma16816(acc[mf][nf], ah[mf], bh[q][h], bh[q][h + 1]);
                    if (ASPLIT) mma16816(acc[mf][nf], al[mf], bh[q][h], bh[q][h + 1]);
                    if (BSPLIT) mma16816(acc[mf][nf], ah[mf], bl[q][h], bl[q][h + 1]);
                }
        }
    }

    // ---- epilogue ----
    const int tg = lane >> 2, tl = lane & 3;
    const float c0 = SCB ? __ldg(cb) : 0.f;
#pragma unroll
    for (int mf = 0; mf < 4; mf++) {
#pragma unroll
        for (int nf = 0; nf < 8; nf++) {
            const int col = col0 + n0 + nf * 8 + tl * 2;
            float b0 = 0.f, b1 = 0.f;
            if (HASBIAS) { b0 = __ldg(bias + col); b1 = __ldg(bias + col + 1); }
            float bc0 = 0.f, bc1 = 0.f;
            if (SCB) { bc0 = __ldg(bv + col) + c0; bc1 = __ldg(bv + col + 1) + c0; }
#pragma unroll
            for (int hrow = 0; hrow < 2; hrow++) {
                const int row = row0 + m0 + mf * 16 + tg + hrow * 8;
                float v0, v1;
                if (SCB) {
                    const float ar = __ldg(av + row);
                    v0 = (acc[mf][nf][hrow * 2 + 0] + ar + bc0) * alpha;
                    v1 = (acc[mf][nf][hrow * 2 + 1] + ar + bc1) * alpha;
                } else {
                    v0 = acc[mf][nf][hrow * 2 + 0] * alpha + b0;
                    v1 = acc[mf][nf][hrow * 2 + 1] * alpha + b1;
                }
                if (WTRANS) {
                    __half h0 = __float2half_rn(v0);
                    __half h1 = __float2half_rn(v1);
                    Chi[cOff + (long long)col * SEQ + row] = h0;
                    Chi[cOff + (long long)(col + 1) * SEQ + row] = h1;
                    if (WLO) {
                        Clo[cOff + (long long)col * SEQ + row] =
                            __float2half_rn(v0 - __half2float(h0));
                        Clo[cOff + (long long)(col + 1) * SEQ + row] =
                            __float2half_rn(v1 - __half2float(h1));
                    }
                } else {
                    const long long off = cOff + (long long)row * N + col;
                    if (WF32) {
                        float2 o; o.x = v0; o.y = v1;
                        *(float2*)(Cf + off) = o;
                    } else {
                        __half h0 = __float2half_rn(v0);
                        __half h1 = __float2half_rn(v1);
                        __half2 th; th.x = h0; th.y = h1;
                        *(__half2*)(Chi + off) = th;
                        if (WLO) {
                            __half2 tlh;
                            tlh.x = __float2half_rn(v0 - __half2float(h0));
                            tlh.y = __float2half_rn(v1 - __half2float(h1));
                            *(__half2*)(Clo + off) = tlh;
                        }
                    }
                }
            }
        }
    }
}

// ---------------- persistent GEMM over (ntz, nty, ntx) tiles ----------------
template <int NS, bool ASPLIT, bool BSPLIT, bool WF32, bool HASBIAS, bool WLO,
          bool SCB>
__global__ void __launch_bounds__(128) mma_gemm_p(
    const __half* __restrict__ Ah_g, const __half* __restrict__ Al_g,
    const __half* __restrict__ Bh_g, const __half* __restrict__ Bl_g,
    const float* __restrict__ bias,
    float* __restrict__ Cf, __half* __restrict__ Chi, __half* __restrict__ Clo,
    int N, int Kld, int Kit, float alpha,
    long long sA, long long sB, long long sC,
    int ntx, int nty, int ntz,
    const float* __restrict__ av, const float* __restrict__ bv,
    const float* __restrict__ cb)
{
    const int total = ntx * nty * ntz;
    const int nxy = ntx * nty;
    for (int t = blockIdx.x; t < total; t += gridDim.x) {
        const int tz = t / nxy;
        const int r = t - tz * nxy;
        const int ty = r / ntx;
        const int tx = r - ty * ntx;
        __syncthreads();
        gemm_core<NS, ASPLIT, BSPLIT, WF32, HASBIAS, WLO, false, SCB>(
            Ah_g + (long long)tz * sA, ASPLIT ? (Al_g + (long long)tz * sA) : nullptr,
            Bh_g + (long long)tz * sB, BSPLIT ? (Bl_g + (long long)tz * sB) : nullptr,
            bias, Cf, Chi, Clo, N, Kld, Kit, alpha,
            ty * 128, tx * 128, (long long)tz * sC,
            SCB ? (av + (long long)tz * SEQ) : nullptr,
            SCB ? (bv + (long long)tz * SEQ) : nullptr, cb);
    }
}

// persistent Z = x @ WZ + bz (2-term B-split, 3-stage, TRANSPOSED hi out)
__global__ void __launch_bounds__(128) zx_gemm_p(
    const __half* __restrict__ xhi,
    const __half* __restrict__ wzth, const __half* __restrict__ wztl,
    const float* __restrict__ bz,
    __half* __restrict__ zth,
    int ntx, int nty)
{
    const int total = ntx * nty;
    for (int t = blockIdx.x; t < total; t += gridDim.x) {
        const int ty = t / ntx;
        const int tx = t - ty * ntx;
        __syncthreads();
        const long long batch = (long long)((ty * 128) >> 11);
        gemm_core<3, false, true, false, true, false, true, false>(
            xhi, nullptr, wzth, wztl, bz,
            nullptr, zth, nullptr, DIM, DIM, DIM, 1.f,
            ty * 128, tx * 128, batch * SEQ * (DIM - 1),
            nullptr, nullptr, nullptr);
    }
}

// smem budgets
#define SMEM_3T  (2 * 4 * 10240)        // 81920
#define SMEM_2T  (3 * 3 * 10240)        // 92160
#define SMEM_1T  (4 * 2 * 10240)        // 81920

// ============================================================================
// helper kernels
// ============================================================================
__global__ void __launch_bounds__(256) convert_split_kernel(
    const float* __restrict__ in, __half* __restrict__ hi,
    __half* __restrict__ lo, long long n4)
{
    long long i = (long long)blockIdx.x * 256 + threadIdx.x;
    if (i >= n4) return;
    float4 v = ((const float4*)in)[i];
    __half h0 = __float2half_rn(v.x), h1 = __float2half_rn(v.y);
    __half h2 = __float2half_rn(v.z), h3 = __float2half_rn(v.w);
    __half2 a, b; a.x = h0; a.y = h1; b.x = h2; b.y = h3;
    ((__half2*)hi)[i * 2 + 0] = a;
    ((__half2*)hi)[i * 2 + 1] = b;
    __half2 c, d;
    c.x = __float2half_rn(v.x - __half2float(h0));
    c.y = __float2half_rn(v.y - __half2float(h1));
    d.x = __float2half_rn(v.z - __half2float(h2));
    d.y = __float2half_rn(v.w - __half2float(h3));
    ((__half2*)lo)[i * 2 + 0] = c;
    ((__half2*)lo)[i * 2 + 1] = d;
}

__global__ void __launch_bounds__(256) mt_reduce_kernel(
    const float* __restrict__ part, __half* __restrict__ hi,
    __half* __restrict__ lo)
{
    const long long n4 = (long long)DIM * DIM / 4;
    long long i = (long long)blockIdx.x * 256 + threadIdx.x;
    if (i >= n4) return;
    const long long stride4 = n4;
    float4 a = ((const float4*)part)[i];
    float4 b = ((const float4*)part)[i + stride4];
    float4 c = ((const float4*)part)[i + 2 * stride4];
    float4 d = ((const float4*)part)[i + 3 * stride4];
    float4 s;
    s.x = (a.x + b.x) + (c.x + d.x);
    s.y = (a.y + b.y) + (c.y + d.y);
    s.z = (a.z + b.z) + (c.z + d.z);
    s.w = (a.w + b.w) + (c.w + d.w);
    __half h0 = __float2half_rn(s.x), h1 = __float2half_rn(s.y);
    __half h2 = __float2half_rn(s.z), h3 = __float2half_rn(s.w);
    __half2 p, q; p.x = h0; p.y = h1; q.x = h2; q.y = h3;
    ((__half2*)hi)[i * 2 + 0] = p;
    ((__half2*)hi)[i * 2 + 1] = q;
    __half2 r, t;
    r.x = __float2half_rn(s.x - __half2float(h0));
    r.y = __float2half_rn(s.y - __half2float(h1));
    t.x = __float2half_rn(s.z - __half2float(h2));
    t.y = __float2half_rn(s.w - __half2float(h3));
    ((__half2*)lo)[i * 2 + 0] = r;
    ((__half2*)lo)[i * 2 + 1] = t;
}

__global__ void __launch_bounds__(256) transpose_split_kernel(
    const float* __restrict__ in, __half* __restrict__ hi,
    __half* __restrict__ lo, int R, int C)
{
    __shared__ float t[32][33];
    const int c0 = blockIdx.x * 32, r0 = blockIdx.y * 32;
    const int tx = threadIdx.x & 31, ty = threadIdx.x >> 5;
#pragma unroll
    for (int j = 0; j < 4; j++)
        t[ty + j * 8][tx] = in[(long long)(r0 + ty + j * 8) * C + c0 + tx];
    __syncthreads();
#pragma unroll
    for (int j = 0; j < 4; j++) {
        int oc = c0 + ty + j * 8;
        float v = t[tx][ty + j * 8];
        long long o = (long long)oc * R + r0 + tx;
        __half h = __float2half_rn(v);
        hi[o] = h;
        lo[o] = __float2half_rn(v - __half2float(h));
    }
}

__global__ void __launch_bounds__(256) uvw_kernel(
    const float* __restrict__ wq, const float* __restrict__ wk,
    const float* __restrict__ bq, const float* __restrict__ bk,
    float* __restrict__ u, float* __restrict__ w, float* __restrict__ cb)
{
    const int d = blockIdx.x * 2 + (threadIdx.x >> 7);
    const int tid = threadIdx.x & 127;
    float su = 0.f, sw = 0.f;
    const float4* wq4 = (const float4*)(wq + (long long)d * DIM);
    const float4* wk4 = (const float4*)(wk + (long long)d * DIM);
    const float4* bk4 = (const float4*)bk;
    const float4* bq4 = (const float4*)bq;
    for (int f = tid; f < DIM / 4; f += 128) {
        float4 a = wq4[f], b = bk4[f];
        su += a.x * b.x + a.y * b.y + a.z * b.z + a.w * b.w;
        float4 c = wk4[f], e = bq4[f];
        sw += c.x * e.x + c.y * e.y + c.z * e.z + c.w * e.w;
    }
#pragma unroll
    for (int o = 16; o; o >>= 1) {
        su += __shfl_xor_sync(0xffffffffu, su, o);
        sw += __shfl_xor_sync(0xffffffffu, sw, o);
    }
    __shared__ float r1[2][4], r2[2][4];
    const int half = threadIdx.x >> 7, wrp = (threadIdx.x >> 5) & 3;
    if ((tid & 31) == 0) { r1[half][wrp] = su; r2[half][wrp] = sw; }
    __syncthreads();
    if (tid == 0) {
        u[d] = (r1[half][0] + r1[half][1]) + (r1[half][2] + r1[half][3]);
        w[d] = (r2[half][0] + r2[half][1]) + (r2[half][2] + r2[half][3]);
    }
    if (d == 0 && tid == 0) {
        float c = 0.f;
        for (int f = 0; f < DIM; f++) c += bq[f] * bk[f];
        cb[0] = c;
    }
}

__global__ void __launch_bounds__(256) av_kernel(
    const float* __restrict__ x, const float* __restrict__ u,
    const float* __restrict__ w, float* __restrict__ av, float* __restrict__ bv)
{
    const long long i = blockIdx.x;
    const float* xr = x + i * DIM;
    const int tid = threadIdx.x;
    float sa = 0.f, sb = 0.f;
    for (int d = tid; d < DIM; d += 256) {
        float xv = xr[d];
        sa += xv * u[d];
        sb += xv * w[d];
    }
    __shared__ float r1[256], r2[256];
    r1[tid] = sa; r2[tid] = sb;
    __syncthreads();
    for (int s = 128; s; s >>= 1) {
        if (tid < s) { r1[tid] += r1[tid + s]; r2[tid] += r2[tid + s]; }
        __syncthreads();
    }
    if (tid == 0) { av[i] = r1[0]; bv[i] = r2[0]; }
}

// bz[d] = sum_e Wp[e][d] * bv[e]   (coalesced across d)
__global__ void __launch_bounds__(256) bz_kernel(
    const float* __restrict__ wp, const float* __restrict__ bvb,
    float* __restrict__ bz)
{
    const int d = blockIdx.x * 256 + threadIdx.x;
    float s = 0.f;
    for (int e = 0; e < DIM; e++) s += wp[(long long)e * DIM + d] * bvb[e];
    bz[d] = s;
}

__global__ void __launch_bounds__(256) softmax2048_kernel(
    float* __restrict__ p, __half* __restrict__ phi)
{
    const long long roff = (long long)blockIdx.x * 2048;
    float* row = p + roff;
    const int tid = threadIdx.x;

    float4 v0 = ((const float4*)row)[tid];
    float4 v1 = ((const float4*)row)[tid + 256];

    float m = fmaxf(fmaxf(fmaxf(v0.x, v0.y), fmaxf(v0.z, v0.w)),
                    fmaxf(fmaxf(v1.x, v1.y), fmaxf(v1.z, v1.w)));
    __shared__ float red[8];
#pragma unroll
    for (int o = 16; o; o >>= 1) m = fmaxf(m, __shfl_xor_sync(0xffffffffu, m, o));
    if ((tid & 31) == 0) red[tid >> 5] = m;
    __syncthreads();
    m = red[0];
#pragma unroll
    for (int i = 1; i < 8; i++) m = fmaxf(m, red[i]);
    __syncthreads();

    v0.x = expf(v0.x - m); v0.y = expf(v0.y - m);
    v0.z = expf(v0.z - m); v0.w = expf(v0.w - m);
    v1.x = expf(v1.x - m); v1.y = expf(v1.y - m);
    v1.z = expf(v1.z - m); v1.w = expf(v1.w - m);

    float s = (v0.x + v0.y) + (v0.z + v0.w) + (v1.x + v1.y) + (v1.z + v1.w);
#pragma unroll
    for (int o = 16; o; o >>= 1) s += __shfl_xor_sync(0xffffffffu, s, o);
    if ((tid & 31) == 0) red[tid >> 5] = s;
    __syncthreads();
    s = ((red[0] + red[1]) + (red[2] + red[3])) +
        ((red[4] + red[5]) + (red[6] + red[7]));
    float inv = 1.0f / s;

    v0.x *= inv; v0.y *= inv; v0.z *= inv; v0.w *= inv;
    v1.x *= inv; v1.y *= inv; v1.z *= inv; v1.w *= inv;

    ((float4*)row)[tid] = v0;
    ((float4*)row)[tid + 256] = v1;

    const float vv[8] = {v0.x, v0.y, v0.z, v0.w, v1.x, v1.y, v1.z, v1.w};
    const long long off[2] = {roff + (long long)tid * 4,
                              roff + (long long)(tid + 256) * 4};
#pragma unroll
    for (int hseg = 0; hseg < 2; hseg++) {
#pragma unroll
        for (int g = 0; g < 2; g++) {
            __half2 th;
            th.x = __float2half_rn(vv[hseg * 4 + g * 2]);
            th.y = __float2half_rn(vv[hseg * 4 + g * 2 + 1]);
            *(__half2*)(phi + off[hseg] + g * 2) = th;
        }
    }
}

// ============================================================================
// host launcher
// ============================================================================
extern "C" void kernel_launch(void* const* d_in, const int* in_sizes, int n_in,
                              void* d_out, int out_size)
{
    const float* x  = (const float*)d_in[0];
    const float* wq = (const float*)d_in[1];
    const float* bq = (const float*)d_in[2];
    const float* wk = (const float*)d_in[3];
    const float* bk = (const float*)d_in[4];
    const float* wv = (const float*)d_in[5];
    const float* bv = (const float*)d_in[6];
    const float* wp = (const float*)d_in[7];
    const float* bp = (const float*)d_in[8];
    float* out = (float*)d_out;

#define SYM(p, s) void* p##_; cudaGetSymbolAddress(&p##_, s);
    SYM(xhi, g_xhi) SYM(xlo, g_xlo)
    SYM(wqsh, g_wqsh) SYM(wqsl, g_wqsl)
    SYM(wksh, g_wksh) SYM(wksl, g_wksl)
    SYM(wvsh, g_wvsh) SYM(wvsl, g_wvsl)
    SYM(wpth, g_wpTh) SYM(wptl, g_wpTl)
    SYM(mtp, g_mtpart) SYM(wzp, g_wzpart)
    SYM(mth, g_mth) SYM(mtl, g_mtl)
    SYM(wzth, g_wzth) SYM(wztl, g_wztl)
    SYM(thi, g_thi) SYM(tlo, g_tlo)
    SYM(zth, g_zth)
    SYM(phi, g_phi)
    SYM(uu, g_u) SYM(ww, g_w) SYM(cc, g_c) SYM(bz, g_bz)
    SYM(avv, g_av) SYM(bvv, g_bv)
    SYM(sfb, g_scores_fb)
#undef SYM
#define HF(p) ((__half*)p##_)

    float* pattn = (out_size >= (long long)(OUT_ELEMS + PATTN_ELEMS))
                       ? (out + OUT_ELEMS) : (float*)sfb_;

    static int nPersist = 0;
    static cudaStream_t s1 = nullptr;
    static cudaEvent_t evFork = nullptr, evX = nullptr, evAux = nullptr,
                       evJoin = nullptr;
    if (nPersist == 0) {
        int nsm = 148;
        cudaDeviceGetAttribute(&nsm, cudaDevAttrMultiProcessorCount, 0);
        nPersist = 2 * nsm;
        cudaStreamCreateWithFlags(&s1, cudaStreamNonBlocking);
        cudaEventCreateWithFlags(&evFork, cudaEventDisableTiming);
        cudaEventCreateWithFlags(&evX, cudaEventDisableTiming);
        cudaEventCreateWithFlags(&evAux, cudaEventDisableTiming);
        cudaEventCreateWithFlags(&evJoin, cudaEventDisableTiming);

        cudaFuncSetAttribute(zx_gemm_p, cudaFuncAttributeMaxDynamicSharedMemorySize, SMEM_2T);
        cudaFuncSetAttribute(mma_gemm_p<2, true,  true,  true,  false, false, false>, cudaFuncAttributeMaxDynamicSharedMemorySize, SMEM_3T);
        cudaFuncSetAttribute(mma_gemm_p<2, true,  true,  false, false, true,  false>, cudaFuncAttributeMaxDynamicSharedMemorySize, SMEM_3T);
        cudaFuncSetAttribute(mma_gemm_p<2, true,  true,  true,  false, false, true >, cudaFuncAttributeMaxDynamicSharedMemorySize, SMEM_3T);
        cudaFuncSetAttribute(mma_gemm_p<4, false, false, true,  true,  false, false>, cudaFuncAttributeMaxDynamicSharedMemorySize, SMEM_1T);
    }
    cudaStream_t s0 = 0;

    // ---- fork ----
    cudaEventRecord(evFork, s0);
    cudaStreamWaitEvent(s1, evFork, 0);

    // ---- s1: x split, aux (scores deps), then WZT -> Z chain ----
    convert_split_kernel<<<(TOK * DIM / 4 + 255) / 256, 256, 0, s1>>>(
        x, HF(xhi), HF(xlo), TOK * DIM / 4);
    cudaEventRecord(evX, s1);
    uvw_kernel<<<DIM / 2, 256, 0, s1>>>(wq, wk, bq, bk,
                                        (float*)uu_, (float*)ww_, (float*)cc_);
    av_kernel<<<TOK, 256, 0, s1>>>(x, (float*)uu_, (float*)ww_, (float*)avv_, (float*)bvv_);
    cudaEventRecord(evAux, s1);

    dim3 gW(DIM / 32, DIM / 32, 1);
    transpose_split_kernel<<<gW, 256, 0, s1>>>(wp, HF(wpth), HF(wptl), DIM, DIM);
    convert_split_kernel<<<(DIM * DIM / 4 + 255) / 256, 256, 0, s1>>>(
        wv, HF(wvsh), HF(wvsl), DIM * DIM / 4);
    bz_kernel<<<DIM / 256, 256, 0, s1>>>(wp, bv, (float*)bz_);

    // WZT = Wp^T @ Wv^T (3-term, split-K partials -> reduce -> hi/lo)
    mma_gemm_p<2, true, true, true, false, false, false><<<nPersist, 128, SMEM_3T, s1>>>(
        HF(wpth), HF(wptl), HF(wvsh), HF(wvsl), nullptr,
        (float*)wzp_, nullptr, nullptr, DIM, DIM, DIM / 4, 1.f,
        DIM / 4, DIM / 4, (long long)DIM * DIM,
        DIM / 128, DIM / 128, 4, nullptr, nullptr, nullptr);
    mt_reduce_kernel<<<(DIM * DIM / 4 + 255) / 256, 256, 0, s1>>>(
        (const float*)wzp_, HF(wzth), HF(wztl));

    // Z^T = (x @ WZ + bz)^T per batch (2-term B-split, transposed hi store)
    zx_gemm_p<<<nPersist, 128, SMEM_2T, s1>>>(
        HF(xhi), HF(wzth), HF(wztl), (const float*)bz_, HF(zth),
        DIM / 128, TOK / 128);
    cudaEventRecord(evJoin, s1);

    // ---- s0: critical chain (wq/wk splits -> MT split-K -> reduce -> t) ----
    convert_split_kernel<<<(DIM * DIM / 4 + 255) / 256, 256, 0, s0>>>(
        wq, HF(wqsh), HF(wqsl), DIM * DIM / 4);
    convert_split_kernel<<<(DIM * DIM / 4 + 255) / 256, 256, 0, s0>>>(
        wk, HF(wksh), HF(wksl), DIM * DIM / 4);

    mma_gemm_p<2, true, true, true, false, false, false><<<nPersist, 128, SMEM_3T, s0>>>(
        HF(wksh), HF(wksl), HF(wqsh), HF(wqsl), nullptr,
        (float*)mtp_, nullptr, nullptr, DIM, DIM, DIM / 4, 1.f,
        DIM / 4, DIM / 4, (long long)DIM * DIM,
        DIM / 128, DIM / 128, 4, nullptr, nullptr, nullptr);
    mt_reduce_kernel<<<(DIM * DIM / 4 + 255) / 256, 256, 0, s0>>>(
        (const float*)mtp_, HF(mth), HF(mtl));

    cudaStreamWaitEvent(s0, evX, 0);
    mma_gemm_p<2, true, true, false, false, true, false><<<nPersist, 128, SMEM_3T, s0>>>(
        HF(xhi), HF(xlo), HF(mth), HF(mtl), nullptr,
        nullptr, HF(thi), HF(tlo), DIM, DIM, DIM, 1.f, 0, 0, 0,
        DIM / 128, TOK / 128, 1, nullptr, nullptr, nullptr);

    // ---- scores (waits only on aux) ----
    cudaStreamWaitEvent(s0, evAux, 0);
    mma_gemm_p<2, true, true, true, false, false, true><<<nPersist, 128, SMEM_3T, s0>>>(
        HF(thi), HF(tlo), HF(xhi), HF(xlo), nullptr, pattn, nullptr, nullptr,
        SEQ, DIM, DIM, 32.f,
        (long long)SEQ * DIM, (long long)SEQ * DIM, (long long)SEQ * SEQ,
        SEQ / 128, SEQ / 128, BATCH,
        (const float*)avv_, (const float*)bvv_, (const float*)cc_);

    softmax2048_kernel<<<TOK, 256, 0, s0>>>(pattn, HF(phi));

    // ---- single 1-term post-softmax GEMM: out = p_hi @ Z + bp ----
    cudaStreamWaitEvent(s0, evJoin, 0);
    mma_gemm_p<4, false, false, true, true, false, false><<<nPersist, 128, SMEM_1T, s0>>>(
        HF(phi), nullptr, HF(zth), nullptr, bp, out, nullptr, nullptr,
        DIM, SEQ, SEQ, 1.f,
        (long long)SEQ * SEQ, (long long)DIM * SEQ, (long long)SEQ * DIM,
        DIM / 128, SEQ / 128, BATCH, nullptr, nullptr, nullptr);
}

// round 17
// speedup vs baseline: 1.2705x; 1.0168x over previous
#include <cuda_runtime.h>
#include <cuda_fp16.h>
#include <cstdint>

// ============================================================================
// Fused attention block via mma.sync (HMMA), fp16 hi/lo split arithmetic.
// Algebraic rewrites:
//   scores = 32*( x(WqWk^T)x^T + a_i + b_j + c )   (q/k projections gone)
//   out    = p·Z + bp,  Z = x·(WvWp) + Wp^T bv     (v AND ctx intermediates gone)
// R17: 2-phase batch-pipelined tail on the proven 2-stream topology —
// softmax+out of batches {0,1} run on s1 under scores of batches {2,3}.
// Terms: 3-term (MT, WZT, t, scores), 2-term (Z), 1-term (out).
// 128x128 tiles, 128 thr/4 warps, 64x64 warp tiles, 2 CTA/SM.
// ============================================================================

#define TOK 8192
#define DIM 1024
#define SEQ 2048
#define BATCH 4

static const long long OUT_ELEMS = (long long)TOK * DIM;
static const long long PATTN_ELEMS = (long long)BATCH * SEQ * SEQ;

// ---------------- device scratch ----------------
__device__ __half g_xhi[TOK * DIM], g_xlo[TOK * DIM];
__device__ __half g_wqsh[DIM * DIM], g_wqsl[DIM * DIM];
__device__ __half g_wksh[DIM * DIM], g_wksl[DIM * DIM];
__device__ __half g_wvsh[DIM * DIM], g_wvsl[DIM * DIM];
__device__ __half g_wpTh[DIM * DIM], g_wpTl[DIM * DIM];
__device__ float  g_mtpart[4 * DIM * DIM];
__device__ float  g_wzpart[4 * DIM * DIM];
__device__ __half g_mth[DIM * DIM], g_mtl[DIM * DIM];
__device__ __half g_wzth[DIM * DIM], g_wztl[DIM * DIM];
__device__ __half g_thi[TOK * DIM], g_tlo[TOK * DIM];
__device__ __half g_zth[TOK * DIM];                       // Z^T[b][d][t] hi
__device__ __half g_phi[BATCH * SEQ * SEQ];
__device__ float  g_u[DIM], g_w[DIM], g_c[1], g_bz[DIM];
__device__ float  g_av[TOK], g_bv[TOK];
__device__ float  g_scores_fb[BATCH * SEQ * SEQ];

// ---------------- PTX helpers ----------------
__device__ __forceinline__ uint32_t smem_u32_f(const void* p) {
    uint32_t a;
    asm("{ .reg .u64 t; cvta.to.shared.u64 t, %1; cvt.u32.u64 %0, t; }"
        : "=r"(a) : "l"(p));
    return a;
}
__device__ __forceinline__ void cp16(uint32_t dst, const void* src) {
    asm volatile("cp.async.cg.shared.global [%0], [%1], 16;" :: "r"(dst), "l"(src));
}
__device__ __forceinline__ void cp_commit() { asm volatile("cp.async.commit_group;"); }
template <int N>
__device__ __forceinline__ void cp_wait() {
    asm volatile("cp.async.wait_group %0;" :: "n"(N));
}
__device__ __forceinline__ void ldm_x4(uint32_t r[4], uint32_t addr) {
    asm volatile("ldmatrix.sync.aligned.m8n8.x4.shared.b16 {%0,%1,%2,%3}, [%4];"
                 : "=r"(r[0]), "=r"(r[1]), "=r"(r[2]), "=r"(r[3]) : "r"(addr));
}
__device__ __forceinline__ void mma16816(float c[4], const uint32_t a[4],
                                         const uint32_t b0, const uint32_t b1) {
    asm volatile(
        "mma.sync.aligned.m16n8k16.row.col.f32.f16.f16.f32 "
        "{%0,%1,%2,%3},{%4,%5,%6,%7},{%8,%9},{%0,%1,%2,%3};"
        : "+f"(c[0]), "+f"(c[1]), "+f"(c[2]), "+f"(c[3])
        : "r"(a[0]), "r"(a[1]), "r"(a[2]), "r"(a[3]), "r"(b0), "r"(b1));
}

#define PITCH 80u
#define TILE_B (128u * PITCH)            // 10240 B

// ============================================================================
// GEMM core for one 128x128 output tile.
// ============================================================================
template <int NS, bool ASPLIT, bool BSPLIT, bool WF32, bool HASBIAS, bool WLO,
          bool WTRANS, bool SCB>
__device__ __forceinline__ void gemm_core(
    const __half* __restrict__ Ah, const __half* __restrict__ Al,
    const __half* __restrict__ Bh, const __half* __restrict__ Bl,
    const float* __restrict__ bias,
    float* __restrict__ Cf, __half* __restrict__ Chi, __half* __restrict__ Clo,
    int N, int Kld, int Kit, float alpha, int row0, int col0, long long cOff,
    const float* __restrict__ av, const float* __restrict__ bv,
    const float* __restrict__ cb)
{
    constexpr uint32_t OF_AH = 0u;
    constexpr uint32_t OF_BH = TILE_B;
    constexpr uint32_t OF_AL = 2u * TILE_B;
    constexpr uint32_t OF_BL = (ASPLIT ? 3u : 2u) * TILE_B;
    constexpr uint32_t STG_SZ = (2u + (ASPLIT ? 1u : 0u) + (BSPLIT ? 1u : 0u)) * TILE_B;

    extern __shared__ char smem_raw[];
    const uint32_t base = smem_u32_f(smem_raw);
    const int tid = threadIdx.x;
    const int warp = tid >> 5, lane = tid & 31;

    long long aOff[4], bOff[4];
    uint32_t dOff[4];
#pragma unroll
    for (int j = 0; j < 4; j++) {
        int c = tid + j * 128;
        int r = c >> 2, q = c & 3;
        aOff[j] = (long long)(row0 + r) * Kld + q * 8;
        bOff[j] = (long long)(col0 + r) * Kld + q * 8;
        dOff[j] = (uint32_t)r * PITCH + (uint32_t)q * 16u;
    }

    const int m0 = (warp & 1) * 64, n0 = (warp >> 1) * 64;
    const uint32_t aLane = (uint32_t)(lane & 15) * PITCH + (uint32_t)(lane >> 4) * 16u;
    const uint32_t bLane = (uint32_t)((lane & 7) + ((lane >> 4) << 3)) * PITCH +
                           (uint32_t)((lane >> 3) & 1) * 16u;

    float acc[4][8][4];
#pragma unroll
    for (int i = 0; i < 4; i++)
#pragma unroll
        for (int j = 0; j < 8; j++)
#pragma unroll
            for (int e = 0; e < 4; e++) acc[i][j][e] = 0.f;

    const int nk = Kit >> 5;

#pragma unroll
    for (int s = 0; s < NS - 1; s++) {
        uint32_t sb = base + (uint32_t)s * STG_SZ;
        long long k0 = (long long)s * 32;
#pragma unroll
        for (int j = 0; j < 4; j++) {
            cp16(sb + OF_AH + dOff[j], Ah + aOff[j] + k0);
            if (ASPLIT) cp16(sb + OF_AL + dOff[j], Al + aOff[j] + k0);
            cp16(sb + OF_BH + dOff[j], Bh + bOff[j] + k0);
            if (BSPLIT) cp16(sb + OF_BL + dOff[j], Bl + bOff[j] + k0);
        }
        cp_commit();
    }

    for (int i = 0; i < nk; i++) {
        const int pend = (nk - 1 - i < NS - 2) ? (nk - 1 - i) : (NS - 2);
        if (pend >= 2)      cp_wait<2>();
        else if (pend == 1) cp_wait<1>();
        else                cp_wait<0>();
        __syncthreads();

        if (i + NS - 1 < nk) {
            const int s = (i + NS - 1) % NS;
            uint32_t sb = base + (uint32_t)s * STG_SZ;
            long long k0 = (long long)(i + NS - 1) * 32;
#pragma unroll
            for (int j = 0; j < 4; j++) {
                cp16(sb + OF_AH + dOff[j], Ah + aOff[j] + k0);
                if (ASPLIT) cp16(sb + OF_AL + dOff[j], Al + aOff[j] + k0);
                cp16(sb + OF_BH + dOff[j], Bh + bOff[j] + k0);
                if (BSPLIT) cp16(sb + OF_BL + dOff[j], Bl + bOff[j] + k0);
            }
            cp_commit();
        }

        const uint32_t sb = base + (uint32_t)(i % NS) * STG_SZ;
#pragma unroll
        for (int ks = 0; ks < 2; ks++) {
            const uint32_t kb = (uint32_t)ks * 32u;
            uint32_t ah[4][4], al[4][4], bh[4][4], bl[4][4];
#pragma unroll
            for (int mf = 0; mf < 4; mf++) {
                uint32_t ro = (uint32_t)(m0 + mf * 16) * PITCH + kb + aLane;
                ldm_x4(ah[mf], sb + OF_AH + ro);
                if (ASPLIT) ldm_x4(al[mf], sb + OF_AL + ro);
            }
#pragma unroll
            for (int q = 0; q < 4; q++) {
                uint32_t ro = (uint32_t)(n0 + q * 16) * PITCH + kb + bLane;
                ldm_x4(bh[q], sb + OF_BH + ro);
                if (BSPLIT) ldm_x4(bl[q], sb + OF_BL + ro);
            }
#pragma unroll
            for (int mf = 0; mf < 4; mf++)
#pragma unroll
                for (int nf = 0; nf < 8; nf++) {
                    const int q = nf >> 1, h = (nf & 1) * 2;
                    mma16816(acc[mf][nf], ah[mf], bh[q][h], bh[q][h + 1]);
                    if (ASPLIT) mma16816(acc[mf][nf], al[mf], bh[q][h], bh[q][h + 1]);
                    if (BSPLIT) mma16816(acc[mf][nf], ah[mf], bl[q][h], bl[q][h + 1]);
                }
        }
    }

    // ---- epilogue ----
    const int tg = lane >> 2, tl = lane & 3;
    const float c0 = SCB ? __ldg(cb) : 0.f;
#pragma unroll
    for (int mf = 0; mf < 4; mf++) {
#pragma unroll
        for (int nf = 0; nf < 8; nf++) {
            const int col = col0 + n0 + nf * 8 + tl * 2;
            float b0 = 0.f, b1 = 0.f;
            if (HASBIAS) { b0 = __ldg(bias + col); b1 = __ldg(bias + col + 1); }
            float bc0 = 0.f, bc1 = 0.f;
            if (SCB) { bc0 = __ldg(bv + col) + c0; bc1 = __ldg(bv + col + 1) + c0; }
#pragma unroll
            for (int hrow = 0; hrow < 2; hrow++) {
                const int row = row0 + m0 + mf * 16 + tg + hrow * 8;
                float v0, v1;
                if (SCB) {
                    const float ar = __ldg(av + row);
                    v0 = (acc[mf][nf][hrow * 2 + 0] + ar + bc0) * alpha;
                    v1 = (acc[mf][nf][hrow * 2 + 1] + ar + bc1) * alpha;
                } else {
                    v0 = acc[mf][nf][hrow * 2 + 0] * alpha + b0;
                    v1 = acc[mf][nf][hrow * 2 + 1] * alpha + b1;
                }
                if (WTRANS) {
                    __half h0 = __float2half_rn(v0);
                    __half h1 = __float2half_rn(v1);
                    Chi[cOff + (long long)col * SEQ + row] = h0;
                    Chi[cOff + (long long)(col + 1) * SEQ + row] = h1;
                    if (WLO) {
                        Clo[cOff + (long long)col * SEQ + row] =
                            __float2half_rn(v0 - __half2float(h0));
                        Clo[cOff + (long long)(col + 1) * SEQ + row] =
                            __float2half_rn(v1 - __half2float(h1));
                    }
                } else {
                    const long long off = cOff + (long long)row * N + col;
                    if (WF32) {
                        float2 o; o.x = v0; o.y = v1;
                        *(float2*)(Cf + off) = o;
                    } else {
                        __half h0 = __float2half_rn(v0);
                        __half h1 = __float2half_rn(v1);
                        __half2 th; th.x = h0; th.y = h1;
                        *(__half2*)(Chi + off) = th;
                        if (WLO) {
                            __half2 tlh;
                            tlh.x = __float2half_rn(v0 - __half2float(h0));
                            tlh.y = __float2half_rn(v1 - __half2float(h1));
                            *(__half2*)(Clo + off) = tlh;
                        }
                    }
                }
            }
        }
    }
}

// ---------------- persistent GEMM over (ntz, nty, ntx) tiles ----------------
template <int NS, bool ASPLIT, bool BSPLIT, bool WF32, bool HASBIAS, bool WLO,
          bool SCB>
__global__ void __launch_bounds__(128) mma_gemm_p(
    const __half* __restrict__ Ah_g, const __half* __restrict__ Al_g,
    const __half* __restrict__ Bh_g, const __half* __restrict__ Bl_g,
    const float* __restrict__ bias,
    float* __restrict__ Cf, __half* __restrict__ Chi, __half* __restrict__ Clo,
    int N, int Kld, int Kit, float alpha,
    long long sA, long long sB, long long sC,
    int ntx, int nty, int ntz,
    const float* __restrict__ av, const float* __restrict__ bv,
    const float* __restrict__ cb)
{
    const int total = ntx * nty * ntz;
    const int nxy = ntx * nty;
    for (int t = blockIdx.x; t < total; t += gridDim.x) {
        const int tz = t / nxy;
        const int r = t - tz * nxy;
        const int ty = r / ntx;
        const int tx = r - ty * ntx;
        __syncthreads();
        gemm_core<NS, ASPLIT, BSPLIT, WF32, HASBIAS, WLO, false, SCB>(
            Ah_g + (long long)tz * sA, ASPLIT ? (Al_g + (long long)tz * sA) : nullptr,
            Bh_g + (long long)tz * sB, BSPLIT ? (Bl_g + (long long)tz * sB) : nullptr,
            bias, Cf, Chi, Clo, N, Kld, Kit, alpha,
            ty * 128, tx * 128, (long long)tz * sC,
            SCB ? (av + (long long)tz * SEQ) : nullptr,
            SCB ? (bv + (long long)tz * SEQ) : nullptr, cb);
    }
}

// persistent Z = x @ WZ + bz (2-term B-split, 3-stage, TRANSPOSED hi out)
__global__ void __launch_bounds__(128) zx_gemm_p(
    const __half* __restrict__ xhi,
    const __half* __restrict__ wzth, const __half* __restrict__ wztl,
    const float* __restrict__ bz,
    __half* __restrict__ zth,
    int ntx, int nty)
{
    const int total = ntx * nty;
    for (int t = blockIdx.x; t < total; t += gridDim.x) {
        const int ty = t / ntx;
        const int tx = t - ty * ntx;
        __syncthreads();
        const long long batch = (long long)((ty * 128) >> 11);
        gemm_core<3, false, true, false, true, false, true, false>(
            xhi, nullptr, wzth, wztl, bz,
            nullptr, zth, nullptr, DIM, DIM, DIM, 1.f,
            ty * 128, tx * 128, batch * SEQ * (DIM - 1),
            nullptr, nullptr, nullptr);
    }
}

// smem budgets
#define SMEM_3T  (2 * 4 * 10240)        // 81920
#define SMEM_2T  (3 * 3 * 10240)        // 92160
#define SMEM_1T  (4 * 2 * 10240)        // 81920

// ============================================================================
// helper kernels
// ============================================================================
__global__ void __launch_bounds__(256) convert_split_kernel(
    const float* __restrict__ in, __half* __restrict__ hi,
    __half* __restrict__ lo, long long n4)
{
    long long i = (long long)blockIdx.x * 256 + threadIdx.x;
    if (i >= n4) return;
    float4 v = ((const float4*)in)[i];
    __half h0 = __float2half_rn(v.x), h1 = __float2half_rn(v.y);
    __half h2 = __float2half_rn(v.z), h3 = __float2half_rn(v.w);
    __half2 a, b; a.x = h0; a.y = h1; b.x = h2; b.y = h3;
    ((__half2*)hi)[i * 2 + 0] = a;
    ((__half2*)hi)[i * 2 + 1] = b;
    __half2 c, d;
    c.x = __float2half_rn(v.x - __half2float(h0));
    c.y = __float2half_rn(v.y - __half2float(h1));
    d.x = __float2half_rn(v.z - __half2float(h2));
    d.y = __float2half_rn(v.w - __half2float(h3));
    ((__half2*)lo)[i * 2 + 0] = c;
    ((__half2*)lo)[i * 2 + 1] = d;
}

__global__ void __launch_bounds__(256) mt_reduce_kernel(
    const float* __restrict__ part, __half* __restrict__ hi,
    __half* __restrict__ lo)
{
    const long long n4 = (long long)DIM * DIM / 4;
    long long i = (long long)blockIdx.x * 256 + threadIdx.x;
    if (i >= n4) return;
    const long long stride4 = n4;
    float4 a = ((const float4*)part)[i];
    float4 b = ((const float4*)part)[i + stride4];
    float4 c = ((const float4*)part)[i + 2 * stride4];
    float4 d = ((const float4*)part)[i + 3 * stride4];
    float4 s;
    s.x = (a.x + b.x) + (c.x + d.x);
    s.y = (a.y + b.y) + (c.y + d.y);
    s.z = (a.z + b.z) + (c.z + d.z);
    s.w = (a.w + b.w) + (c.w + d.w);
    __half h0 = __float2half_rn(s.x), h1 = __float2half_rn(s.y);
    __half h2 = __float2half_rn(s.z), h3 = __float2half_rn(s.w);
    __half2 p, q; p.x = h0; p.y = h1; q.x = h2; q.y = h3;
    ((__half2*)hi)[i * 2 + 0] = p;
    ((__half2*)hi)[i * 2 + 1] = q;
    __half2 r, t;
    r.x = __float2half_rn(s.x - __half2float(h0));
    r.y = __float2half_rn(s.y - __half2float(h1));
    t.x = __float2half_rn(s.z - __half2float(h2));
    t.y = __float2half_rn(s.w - __half2float(h3));
    ((__half2*)lo)[i * 2 + 0] = r;
    ((__half2*)lo)[i * 2 + 1] = t;
}

__global__ void __launch_bounds__(256) transpose_split_kernel(
    const float* __restrict__ in, __half* __restrict__ hi,
    __half* __restrict__ lo, int R, int C)
{
    __shared__ float t[32][33];
    const int c0 = blockIdx.x * 32, r0 = blockIdx.y * 32;
    const int tx = threadIdx.x & 31, ty = threadIdx.x >> 5;
#pragma unroll
    for (int j = 0; j < 4; j++)
        t[ty + j * 8][tx] = in[(long long)(r0 + ty + j * 8) * C + c0 + tx];
    __syncthreads();
#pragma unroll
    for (int j = 0; j < 4; j++) {
        int oc = c0 + ty + j * 8;
        float v = t[tx][ty + j * 8];
        long long o = (long long)oc * R + r0 + tx;
        __half h = __float2half_rn(v);
        hi[o] = h;
        lo[o] = __float2half_rn(v - __half2float(h));
    }
}

__global__ void __launch_bounds__(256) uvw_kernel(
    const float* __restrict__ wq, const float* __restrict__ wk,
    const float* __restrict__ bq, const float* __restrict__ bk,
    float* __restrict__ u, float* __restrict__ w, float* __restrict__ cb)
{
    const int d = blockIdx.x * 2 + (threadIdx.x >> 7);
    const int tid = threadIdx.x & 127;
    float su = 0.f, sw = 0.f;
    const float4* wq4 = (const float4*)(wq + (long long)d * DIM);
    const float4* wk4 = (const float4*)(wk + (long long)d * DIM);
    const float4* bk4 = (const float4*)bk;
    const float4* bq4 = (const float4*)bq;
    for (int f = tid; f < DIM / 4; f += 128) {
        float4 a = wq4[f], b = bk4[f];
        su += a.x * b.x + a.y * b.y + a.z * b.z + a.w * b.w;
        float4 c = wk4[f], e = bq4[f];
        sw += c.x * e.x + c.y * e.y + c.z * e.z + c.w * e.w;
    }
#pragma unroll
    for (int o = 16; o; o >>= 1) {
        su += __shfl_xor_sync(0xffffffffu, su, o);
        sw += __shfl_xor_sync(0xffffffffu, sw, o);
    }
    __shared__ float r1[2][4], r2[2][4];
    const int half = threadIdx.x >> 7, wrp = (threadIdx.x >> 5) & 3;
    if ((tid & 31) == 0) { r1[half][wrp] = su; r2[half][wrp] = sw; }
    __syncthreads();
    if (tid == 0) {
        u[d] = (r1[half][0] + r1[half][1]) + (r1[half][2] + r1[half][3]);
        w[d] = (r2[half][0] + r2[half][1]) + (r2[half][2] + r2[half][3]);
    }
    if (d == 0 && tid == 0) {
        float c = 0.f;
        for (int f = 0; f < DIM; f++) c += bq[f] * bk[f];
        cb[0] = c;
    }
}

__global__ void __launch_bounds__(256) av_kernel(
    const float* __restrict__ x, const float* __restrict__ u,
    const float* __restrict__ w, float* __restrict__ av, float* __restrict__ bv)
{
    const long long i = blockIdx.x;
    const float* xr = x + i * DIM;
    const int tid = threadIdx.x;
    float sa = 0.f, sb = 0.f;
    for (int d = tid; d < DIM; d += 256) {
        float xv = xr[d];
        sa += xv * u[d];
        sb += xv * w[d];
    }
    __shared__ float r1[256], r2[256];
    r1[tid] = sa; r2[tid] = sb;
    __syncthreads();
    for (int s = 128; s; s >>= 1) {
        if (tid < s) { r1[tid] += r1[tid + s]; r2[tid] += r2[tid + s]; }
        __syncthreads();
    }
    if (tid == 0) { av[i] = r1[0]; bv[i] = r2[0]; }
}

__global__ void __launch_bounds__(256) bz_kernel(
    const float* __restrict__ wp, const float* __restrict__ bvb,
    float* __restrict__ bz)
{
    const int d = blockIdx.x * 256 + threadIdx.x;
    float s = 0.f;
    for (int e = 0; e < DIM; e++) s += wp[(long long)e * DIM + d] * bvb[e];
    bz[d] = s;
}

__global__ void __launch_bounds__(256) softmax2048_kernel(
    float* __restrict__ p, __half* __restrict__ phi)
{
    const long long roff = (long long)blockIdx.x * 2048;
    float* row = p + roff;
    const int tid = threadIdx.x;

    float4 v0 = ((const float4*)row)[tid];
    float4 v1 = ((const float4*)row)[tid + 256];

    float m = fmaxf(fmaxf(fmaxf(v0.x, v0.y), fmaxf(v0.z, v0.w)),
                    fmaxf(fmaxf(v1.x, v1.y), fmaxf(v1.z, v1.w)));
    __shared__ float red[8];
#pragma unroll
    for (int o = 16; o; o >>= 1) m = fmaxf(m, __shfl_xor_sync(0xffffffffu, m, o));
    if ((tid & 31) == 0) red[tid >> 5] = m;
    __syncthreads();
    m = red[0];
#pragma unroll
    for (int i = 1; i < 8; i++) m = fmaxf(m, red[i]);
    __syncthreads();

    v0.x = expf(v0.x - m); v0.y = expf(v0.y - m);
    v0.z = expf(v0.z - m); v0.w = expf(v0.w - m);
    v1.x = expf(v1.x - m); v1.y = expf(v1.y - m);
    v1.z = expf(v1.z - m); v1.w = expf(v1.w - m);

    float s = (v0.x + v0.y) + (v0.z + v0.w) + (v1.x + v1.y) + (v1.z + v1.w);
#pragma unroll
    for (int o = 16; o; o >>= 1) s += __shfl_xor_sync(0xffffffffu, s, o);
    if ((tid & 31) == 0) red[tid >> 5] = s;
    __syncthreads();
    s = ((red[0] + red[1]) + (red[2] + red[3])) +
        ((red[4] + red[5]) + (red[6] + red[7]));
    float inv = 1.0f / s;

    v0.x *= inv; v0.y *= inv; v0.z *= inv; v0.w *= inv;
    v1.x *= inv; v1.y *= inv; v1.z *= inv; v1.w *= inv;

    ((float4*)row)[tid] = v0;
    ((float4*)row)[tid + 256] = v1;

    const float vv[8] = {v0.x, v0.y, v0.z, v0.w, v1.x, v1.y, v1.z, v1.w};
    const long long off[2] = {roff + (long long)tid * 4,
                              roff + (long long)(tid + 256) * 4};
#pragma unroll
    for (int hseg = 0; hseg < 2; hseg++) {
#pragma unroll
        for (int g = 0; g < 2; g++) {
            __half2 th;
            th.x = __float2half_rn(vv[hseg * 4 + g * 2]);
            th.y = __float2half_rn(vv[hseg * 4 + g * 2 + 1]);
            *(__half2*)(phi + off[hseg] + g * 2) = th;
        }
    }
}

// ============================================================================
// host launcher
// ============================================================================
extern "C" void kernel_launch(void* const* d_in, const int* in_sizes, int n_in,
                              void* d_out, int out_size)
{
    const float* x  = (const float*)d_in[0];
    const float* wq = (const float*)d_in[1];
    const float* bq = (const float*)d_in[2];
    const float* wk = (const float*)d_in[3];
    const float* bk = (const float*)d_in[4];
    const float* wv = (const float*)d_in[5];
    const float* bv = (const float*)d_in[6];
    const float* wp = (const float*)d_in[7];
    const float* bp = (const float*)d_in[8];
    float* out = (float*)d_out;

#define SYM(p, s) void* p##_; cudaGetSymbolAddress(&p##_, s);
    SYM(xhi, g_xhi) SYM(xlo, g_xlo)
    SYM(wqsh, g_wqsh) SYM(wqsl, g_wqsl)
    SYM(wksh, g_wksh) SYM(wksl, g_wksl)
    SYM(wvsh, g_wvsh) SYM(wvsl, g_wvsl)
    SYM(wpth, g_wpTh) SYM(wptl, g_wpTl)
    SYM(mtp, g_mtpart) SYM(wzp, g_wzpart)
    SYM(mth, g_mth) SYM(mtl, g_mtl)
    SYM(wzth, g_wzth) SYM(wztl, g_wztl)
    SYM(thi, g_thi) SYM(tlo, g_tlo)
    SYM(zth, g_zth)
    SYM(phi, g_phi)
    SYM(uu, g_u) SYM(ww, g_w) SYM(cc, g_c) SYM(bz, g_bz)
    SYM(avv, g_av) SYM(bvv, g_bv)
    SYM(sfb, g_scores_fb)
#undef SYM
#define HF(p) ((__half*)p##_)

    float* pattn = (out_size >= (long long)(OUT_ELEMS + PATTN_ELEMS))
                       ? (out + OUT_ELEMS) : (float*)sfb_;

    static int nPersist = 0;
    static cudaStream_t s1 = nullptr;
    static cudaEvent_t evFork = nullptr, evX = nullptr, evAux = nullptr,
                       evJoin = nullptr, evS01 = nullptr, evS23 = nullptr,
                       evEnd = nullptr;
    if (nPersist == 0) {
        int nsm = 148;
        cudaDeviceGetAttribute(&nsm, cudaDevAttrMultiProcessorCount, 0);
        nPersist = 2 * nsm;
        cudaStreamCreateWithFlags(&s1, cudaStreamNonBlocking);
        cudaEventCreateWithFlags(&evFork, cudaEventDisableTiming);
        cudaEventCreateWithFlags(&evX, cudaEventDisableTiming);
        cudaEventCreateWithFlags(&evAux, cudaEventDisableTiming);
        cudaEventCreateWithFlags(&evJoin, cudaEventDisableTiming);
        cudaEventCreateWithFlags(&evS01, cudaEventDisableTiming);
        cudaEventCreateWithFlags(&evS23, cudaEventDisableTiming);
        cudaEventCreateWithFlags(&evEnd, cudaEventDisableTiming);

        cudaFuncSetAttribute(zx_gemm_p, cudaFuncAttributeMaxDynamicSharedMemorySize, SMEM_2T);
        cudaFuncSetAttribute(mma_gemm_p<2, true,  true,  true,  false, false, false>, cudaFuncAttributeMaxDynamicSharedMemorySize, SMEM_3T);
        cudaFuncSetAttribute(mma_gemm_p<2, true,  true,  false, false, true,  false>, cudaFuncAttributeMaxDynamicSharedMemorySize, SMEM_3T);
        cudaFuncSetAttribute(mma_gemm_p<2, true,  true,  true,  false, false, true >, cudaFuncAttributeMaxDynamicSharedMemorySize, SMEM_3T);
        cudaFuncSetAttribute(mma_gemm_p<4, false, false, true,  true,  false, false>, cudaFuncAttributeMaxDynamicSharedMemorySize, SMEM_1T);
    }
    cudaStream_t s0 = 0;

    const long long sTD = (long long)SEQ * DIM;
    const long long sSS = (long long)SEQ * SEQ;

    // ---- fork ----
    cudaEventRecord(evFork, s0);
    cudaStreamWaitEvent(s1, evFork, 0);

    // ---- s1: x split, aux, then WZT -> Z chain ----
    convert_split_kernel<<<(TOK * DIM / 4 + 255) / 256, 256, 0, s1>>>(
        x, HF(xhi), HF(xlo), TOK * DIM / 4);
    cudaEventRecord(evX, s1);
    uvw_kernel<<<DIM / 2, 256, 0, s1>>>(wq, wk, bq, bk,
                                        (float*)uu_, (float*)ww_, (float*)cc_);
    av_kernel<<<TOK, 256, 0, s1>>>(x, (float*)uu_, (float*)ww_, (float*)avv_, (float*)bvv_);
    cudaEventRecord(evAux, s1);

    dim3 gW(DIM / 32, DIM / 32, 1);
    transpose_split_kernel<<<gW, 256, 0, s1>>>(wp, HF(wpth), HF(wptl), DIM, DIM);
    convert_split_kernel<<<(DIM * DIM / 4 + 255) / 256, 256, 0, s1>>>(
        wv, HF(wvsh), HF(wvsl), DIM * DIM / 4);
    bz_kernel<<<DIM / 256, 256, 0, s1>>>(wp, bv, (float*)bz_);

    mma_gemm_p<2, true, true, true, false, false, false><<<nPersist, 128, SMEM_3T, s1>>>(
        HF(wpth), HF(wptl), HF(wvsh), HF(wvsl), nullptr,
        (float*)wzp_, nullptr, nullptr, DIM, DIM, DIM / 4, 1.f,
        DIM / 4, DIM / 4, (long long)DIM * DIM,
        DIM / 128, DIM / 128, 4, nullptr, nullptr, nullptr);
    mt_reduce_kernel<<<(DIM * DIM / 4 + 255) / 256, 256, 0, s1>>>(
        (const float*)wzp_, HF(wzth), HF(wztl));

    zx_gemm_p<<<nPersist, 128, SMEM_2T, s1>>>(
        HF(xhi), HF(wzth), HF(wztl), (const float*)bz_, HF(zth),
        DIM / 128, TOK / 128);
    cudaEventRecord(evJoin, s1);   // Z ready (s1 in-order after this)

    // ---- s0: critical chain (wq/wk splits -> MT split-K -> reduce -> t) ----
    convert_split_kernel<<<(DIM * DIM / 4 + 255) / 256, 256, 0, s0>>>(
        wq, HF(wqsh), HF(wqsl), DIM * DIM / 4);
    convert_split_kernel<<<(DIM * DIM / 4 + 255) / 256, 256, 0, s0>>>(
        wk, HF(wksh), HF(wksl), DIM * DIM / 4);

    mma_gemm_p<2, true, true, true, false, false, false><<<nPersist, 128, SMEM_3T, s0>>>(
        HF(wksh), HF(wksl), HF(wqsh), HF(wqsl), nullptr,
        (float*)mtp_, nullptr, nullptr, DIM, DIM, DIM / 4, 1.f,
        DIM / 4, DIM / 4, (long long)DIM * DIM,
        DIM / 128, DIM / 128, 4, nullptr, nullptr, nullptr);
    mt_reduce_kernel<<<(DIM * DIM / 4 + 255) / 256, 256, 0, s0>>>(
        (const float*)mtp_, HF(mth), HF(mtl));

    cudaStreamWaitEvent(s0, evX, 0);
    mma_gemm_p<2, true, true, false, false, true, false><<<nPersist, 128, SMEM_3T, s0>>>(
        HF(xhi), HF(xlo), HF(mth), HF(mtl), nullptr,
        nullptr, HF(thi), HF(tlo), DIM, DIM, DIM, 1.f, 0, 0, 0,
        DIM / 128, TOK / 128, 1, nullptr, nullptr, nullptr);

    // ---- scores in two batch-halves on s0 ----
    cudaStreamWaitEvent(s0, evAux, 0);
    // scores(b0,b1): 512 tiles
    mma_gemm_p<2, true, true, true, false, false, true><<<512, 128, SMEM_3T, s0>>>(
        HF(thi), HF(tlo), HF(xhi), HF(xlo), nullptr, pattn, nullptr, nullptr,
        SEQ, DIM, DIM, 32.f, sTD, sTD, sSS,
        SEQ / 128, SEQ / 128, 2,
        (const float*)avv_, (const float*)bvv_, (const float*)cc_);
    cudaEventRecord(evS01, s0);
    // scores(b2,b3): 512 tiles
    mma_gemm_p<2, true, true, true, false, false, true><<<512, 128, SMEM_3T, s0>>>(
        HF(thi) + 2 * sTD, HF(tlo) + 2 * sTD, HF(xhi) + 2 * sTD, HF(xlo) + 2 * sTD,
        nullptr, pattn + 2 * sSS, nullptr, nullptr,
        SEQ, DIM, DIM, 32.f, sTD, sTD, sSS,
        SEQ / 128, SEQ / 128, 2,
        (const float*)avv_ + 2 * SEQ, (const float*)bvv_ + 2 * SEQ,
        (const float*)cc_);
    cudaEventRecord(evS23, s0);

    // ---- s1 (Z already in-order): softmax+out b01 under scores b23 ----
    cudaStreamWaitEvent(s1, evS01, 0);
    softmax2048_kernel<<<2 * SEQ, 256, 0, s1>>>(pattn, HF(phi));
    mma_gemm_p<4, false, false, true, true, false, false><<<256, 128, SMEM_1T, s1>>>(
        HF(phi), nullptr, HF(zth), nullptr, bp, out, nullptr, nullptr,
        DIM, SEQ, SEQ, 1.f, sSS, sTD, sTD,
        DIM / 128, SEQ / 128, 2, nullptr, nullptr, nullptr);
    // softmax+out b23
    cudaStreamWaitEvent(s1, evS23, 0);
    softmax2048_kernel<<<2 * SEQ, 256, 0, s1>>>(pattn + 2 * sSS, HF(phi) + 2 * sSS);
    mma_gemm_p<4, false, false, true, true, false, false><<<256, 128, SMEM_1T, s1>>>(
        HF(phi) + 2 * sSS, nullptr, HF(zth) + 2 * sTD, nullptr, bp,
        out + 2 * sTD, nullptr, nullptr,
        DIM, SEQ, SEQ, 1.f, sSS, sTD, sTD,
        DIM / 128, SEQ / 128, 2, nullptr, nullptr, nullptr);
    cudaEventRecord(evEnd, s1);

    // ---- join back to s0 ----
    cudaStreamWaitEvent(s0, evEnd, 0);
}